// round 1
// baseline (speedup 1.0000x reference)
#include <cuda_runtime.h>

#define N    4096
#define NJ   16          // j-chunks
#define JC   (N / NJ)    // 256 j per chunk
#define IB   128         // i per block (1 per thread)
#define NBI  (N / IB)    // 32 i-blocks

// Per-particle precomputed data:
//   slot 0: {t, ra, dec, psi}
//   slot 1: {mc/30, f_isco*log2e/100, log2(dist), 0}
__device__ float4 g_pp[N * 2];
// Partial feature sums per j-chunk (fixed-order reduction => deterministic)
//   [chunk][i][0] = {dt, sky, mass_sim, freq_ov}
//   [chunk][i][1] = {dist_ratio, dpsi, dra, ddec}
__device__ float4 g_part[NJ][N][2];

__device__ __forceinline__ float f_ex2(float x) {
    float r; asm("ex2.approx.ftz.f32 %0, %1;" : "=f"(r) : "f"(x)); return r;
}
__device__ __forceinline__ float f_lg2(float x) {
    float r; asm("lg2.approx.ftz.f32 %0, %1;" : "=f"(r) : "f"(x)); return r;
}
__device__ __forceinline__ float f_rcp(float x) {
    float r; asm("rcp.approx.ftz.f32 %0, %1;" : "=f"(r) : "f"(x)); return r;
}
__device__ __forceinline__ float f_sqrt(float x) {
    float r; asm("sqrt.approx.ftz.f32 %0, %1;" : "=f"(r) : "f"(x)); return r;
}

// ---------------------------------------------------------------------------
// Kernel 1: per-particle invariants
// ---------------------------------------------------------------------------
__global__ void prep_kernel(const float* __restrict__ p) {
    int i = blockIdx.x * blockDim.x + threadIdx.x;
    if (i >= N) return;
    const float* q = p + i * 15;
    float m1 = q[0] * 95.0f + 5.0f;
    float m2 = q[1] * 95.0f + 5.0f;
    float dist = q[2] * 2950.0f + 50.0f;
    // mc = (m1*m2)^0.6 / (m1+m2)^0.2
    float mc = f_ex2(0.6f * f_lg2(m1 * m2) - 0.2f * f_lg2(m1 + m2));
    float fisco = 220.0f * f_rcp(m1 + m2);
    const float LOG2E_100 = 1.4426950408889634f / 100.0f;
    g_pp[i * 2 + 0] = make_float4(q[5], q[3], q[4], q[7]);
    g_pp[i * 2 + 1] = make_float4(mc * (1.0f / 30.0f), fisco * LOG2E_100,
                                  f_lg2(dist), 0.0f);
}

// ---------------------------------------------------------------------------
// Kernel 2: pairwise feature partial sums
// grid = (NBI, NJ), block = IB threads; thread t of block bx owns i = bx*IB+t
// and sums over j in [by*JC, by*JC+JC).
// ---------------------------------------------------------------------------
__global__ void __launch_bounds__(IB) pairwise_kernel() {
    __shared__ float4 sj[JC * 2];   // 8 KB

    const int i  = blockIdx.x * IB + threadIdx.x;
    const int j0 = blockIdx.y * JC;

    // stage j-chunk into smem
    #pragma unroll
    for (int k = threadIdx.x; k < JC * 2; k += IB)
        sj[k] = g_pp[j0 * 2 + k];
    __syncthreads();

    const float4 a0 = g_pp[i * 2 + 0];
    const float4 a1 = g_pp[i * 2 + 1];

    float s_dt = 0.f, s_sky = 0.f, s_ms = 0.f, s_fo = 0.f;
    float s_dr = 0.f, s_dp = 0.f, s_ra = 0.f, s_de = 0.f;

    #pragma unroll 4
    for (int j = 0; j < JC; ++j) {
        const float4 b0 = sj[j * 2 + 0];
        const float4 b1 = sj[j * 2 + 1];
        float ddt = a0.x - b0.x;
        float dra = a0.y - b0.y;
        float dde = a0.z - b0.z;
        float dps = a0.w - b0.w;
        s_dt += fabsf(ddt);
        s_ra += fabsf(dra);
        s_de += fabsf(dde);
        s_dp += fabsf(dps);
        s_sky += f_sqrt(fmaf(dra, dra, dde * dde));
        s_ms  += f_rcp(1.0f + fabsf(a1.x - b1.x));
        s_fo  += f_ex2(-fabsf(a1.y - b1.y));
        s_dr  += f_ex2(-fabsf(a1.z - b1.z));
    }

    g_part[blockIdx.y][i][0] = make_float4(s_dt, s_sky, s_ms, s_fo);
    g_part[blockIdx.y][i][1] = make_float4(s_dr, s_dp, s_ra, s_de);
}

// ---------------------------------------------------------------------------
// Kernel 3: reduce partials (fixed order) + MLP + LayerNorm + GELU(exact) + out
// ---------------------------------------------------------------------------
__global__ void __launch_bounds__(256) finish_kernel(
    const float* __restrict__ W1, const float* __restrict__ b1,
    const float* __restrict__ ln_g, const float* __restrict__ ln_b,
    const float* __restrict__ W2, const float* __restrict__ b2,
    float* __restrict__ out)
{
    __shared__ float sW1[8 * 32];
    __shared__ float sW2[32 * 16];
    __shared__ float sb1[32], sg[32], sbeta[32], sb2[16];

    for (int k = threadIdx.x; k < 256; k += blockDim.x) sW1[k] = W1[k];
    for (int k = threadIdx.x; k < 512; k += blockDim.x) sW2[k] = W2[k];
    if (threadIdx.x < 32) {
        sb1[threadIdx.x]   = b1[threadIdx.x];
        sg[threadIdx.x]    = ln_g[threadIdx.x];
        sbeta[threadIdx.x] = ln_b[threadIdx.x];
        if (threadIdx.x < 16) sb2[threadIdx.x] = b2[threadIdx.x];
    }
    __syncthreads();

    const int i = blockIdx.x * blockDim.x + threadIdx.x;
    if (i >= N) return;

    // reduce j-chunk partials in fixed order
    float4 t0 = make_float4(0.f, 0.f, 0.f, 0.f);
    float4 t1 = make_float4(0.f, 0.f, 0.f, 0.f);
    #pragma unroll
    for (int c = 0; c < NJ; ++c) {
        float4 p0 = g_part[c][i][0];
        float4 p1 = g_part[c][i][1];
        t0.x += p0.x; t0.y += p0.y; t0.z += p0.z; t0.w += p0.w;
        t1.x += p1.x; t1.y += p1.y; t1.z += p1.z; t1.w += p1.w;
    }

    // diag = [0,0,1,1,1,0,0,0] (exactly the self-pair contribution), /(n-1)
    const float inv = 1.0f / (float)(N - 1);
    float x[8];
    x[0] = t0.x * inv;
    x[1] = t0.y * inv;
    x[2] = (t0.z - 1.0f) * inv;
    x[3] = (t0.w - 1.0f) * inv;
    x[4] = (t1.x - 1.0f) * inv;
    x[5] = t1.y * inv;
    x[6] = t1.z * inv;
    x[7] = t1.w * inv;

    // h = x @ W1 + b1
    float h[32];
    #pragma unroll
    for (int k = 0; k < 32; ++k) {
        float acc = sb1[k];
        #pragma unroll
        for (int f = 0; f < 8; ++f)
            acc = fmaf(x[f], sW1[f * 32 + k], acc);
        h[k] = acc;
    }

    // LayerNorm (ddof=0)
    float mu = 0.f;
    #pragma unroll
    for (int k = 0; k < 32; ++k) mu += h[k];
    mu *= (1.0f / 32.0f);
    float var = 0.f;
    #pragma unroll
    for (int k = 0; k < 32; ++k) {
        float d = h[k] - mu;
        var = fmaf(d, d, var);
    }
    var *= (1.0f / 32.0f);
    float rs = rsqrtf(var + 1e-5f);

    // normalize + affine + exact GELU: v * 0.5*(1+erf(v/sqrt(2)))
    #pragma unroll
    for (int k = 0; k < 32; ++k) {
        float v = fmaf((h[k] - mu) * rs, sg[k], sbeta[k]);
        h[k] = 0.5f * v * (1.0f + erff(v * 0.7071067811865475f));
    }

    // out = h @ W2 + b2
    float o[16];
    #pragma unroll
    for (int oo = 0; oo < 16; ++oo) {
        float acc = sb2[oo];
        #pragma unroll
        for (int k = 0; k < 32; ++k)
            acc = fmaf(h[k], sW2[k * 16 + oo], acc);
        o[oo] = acc;
    }
    float4* op = reinterpret_cast<float4*>(out + i * 16);
    op[0] = make_float4(o[0],  o[1],  o[2],  o[3]);
    op[1] = make_float4(o[4],  o[5],  o[6],  o[7]);
    op[2] = make_float4(o[8],  o[9],  o[10], o[11]);
    op[3] = make_float4(o[12], o[13], o[14], o[15]);
}

extern "C" void kernel_launch(void* const* d_in, const int* in_sizes, int n_in,
                              void* d_out, int out_size) {
    const float* params = (const float*)d_in[0];
    const float* W1     = (const float*)d_in[1];
    const float* b1     = (const float*)d_in[2];
    const float* ln_g   = (const float*)d_in[3];
    const float* ln_b   = (const float*)d_in[4];
    const float* W2     = (const float*)d_in[5];
    const float* b2     = (const float*)d_in[6];
    float* out = (float*)d_out;

    prep_kernel<<<N / 256, 256>>>(params);
    pairwise_kernel<<<dim3(NBI, NJ), IB>>>();
    finish_kernel<<<N / 256, 256>>>(W1, b1, ln_g, ln_b, W2, b2, out);
}

// round 2
// speedup vs baseline: 1.1393x; 1.1393x over previous
#include <cuda_runtime.h>

#define N    4096
#define NJ   16          // j-chunks
#define JC   (N / NJ)    // 256 j per chunk
#define IB   128         // i per block (1 per thread)
#define NBI  (N / IB)    // 32 i-blocks

// Partial feature sums per j-chunk (fixed-order reduction => deterministic)
//   [chunk][i][0] = {dt, sky, mass_sim, freq_ov}
//   [chunk][i][1] = {dist_ratio, dpsi, dra, ddec}
__device__ float4 g_part[NJ][N][2];

__device__ __forceinline__ float f_ex2(float x) {
    float r; asm("ex2.approx.ftz.f32 %0, %1;" : "=f"(r) : "f"(x)); return r;
}
__device__ __forceinline__ float f_lg2(float x) {
    float r; asm("lg2.approx.ftz.f32 %0, %1;" : "=f"(r) : "f"(x)); return r;
}
__device__ __forceinline__ float f_rcp(float x) {
    float r; asm("rcp.approx.ftz.f32 %0, %1;" : "=f"(r) : "f"(x)); return r;
}
__device__ __forceinline__ float f_sqrt(float x) {
    float r; asm("sqrt.approx.ftz.f32 %0, %1;" : "=f"(r) : "f"(x)); return r;
}

// Per-particle invariants:
//   t, ra, dec, psi            (kinematics)
//   mc30 = chirp_mass / 30
//   E  = exp(+f_isco/100),  RE = exp(-f_isco/100)
//     -> exp(-|fa-fb|/100) = min(Ea*REb, Eb*REa)     [no per-pair MUFU]
//   D  = dist,              RD = 1/dist
//     -> min(da,db)/max(da,db) = min(Da*RDb, Db*RDa) [no per-pair MUFU]
struct Inv { float t, ra, dec, psi, mc30, E, RE, D, RD; };

__device__ __forceinline__ Inv compute_inv(const float* __restrict__ p, int idx) {
    const float* q = p + idx * 15;
    float p0 = q[0], p1 = q[1], p2 = q[2];
    float p3 = q[3], p4 = q[4], p5 = q[5], p7 = q[7];
    float m1 = p0 * 95.0f + 5.0f;
    float m2 = p1 * 95.0f + 5.0f;
    float msum = m1 + m2;
    // mc = (m1*m2)^0.6 / (m1+m2)^0.2
    float mc = f_ex2(0.6f * f_lg2(m1 * m2) - 0.2f * f_lg2(msum));
    // x = (f_isco/100)*log2(e),  f_isco = 220/msum
    const float C = 220.0f * 1.4426950408889634f * 0.01f;
    float x = C * f_rcp(msum);
    Inv v;
    v.t = p5; v.ra = p3; v.dec = p4; v.psi = p7;
    v.mc30 = mc * (1.0f / 30.0f);
    v.E  = f_ex2(x);
    v.RE = f_ex2(-x);
    v.D  = p2 * 2950.0f + 50.0f;
    v.RD = f_rcp(v.D);
    return v;
}

// ---------------------------------------------------------------------------
// Pairwise kernel (prep fused): grid (NBI, NJ), IB threads.
// Thread t of block (bx,by) owns i = bx*IB+t, sums over j in by's chunk.
// ---------------------------------------------------------------------------
__global__ void __launch_bounds__(IB) pairwise_kernel(const float* __restrict__ p) {
    __shared__ float4 sj0[JC];   // t, ra, dec, psi
    __shared__ float4 sj1[JC];   // mc30, E, RE, 0
    __shared__ float2 sj2[JC];   // D, RD

    const int i  = blockIdx.x * IB + threadIdx.x;
    const int j0 = blockIdx.y * JC;

    // compute j-side invariants into smem (2 per thread)
    for (int k = threadIdx.x; k < JC; k += IB) {
        Inv v = compute_inv(p, j0 + k);
        sj0[k] = make_float4(v.t, v.ra, v.dec, v.psi);
        sj1[k] = make_float4(v.mc30, v.E, v.RE, 0.0f);
        sj2[k] = make_float2(v.D, v.RD);
    }
    Inv a = compute_inv(p, i);
    __syncthreads();

    float s_dt = 0.f, s_sky = 0.f, s_ms = 0.f, s_fo = 0.f;
    float s_dr = 0.f, s_dp = 0.f, s_ra = 0.f, s_de = 0.f;

    #pragma unroll 4
    for (int j = 0; j < JC; ++j) {
        const float4 b0 = sj0[j];
        const float4 b1 = sj1[j];
        const float2 b2 = sj2[j];
        float ddt = a.t   - b0.x;
        float dra = a.ra  - b0.y;
        float dde = a.dec - b0.z;
        float dps = a.psi - b0.w;
        s_dt += fabsf(ddt);
        s_ra += fabsf(dra);
        s_de += fabsf(dde);
        s_dp += fabsf(dps);
        s_sky += f_sqrt(fmaf(dra, dra, dde * dde));
        s_ms  += f_rcp(1.0f + fabsf(a.mc30 - b1.x));
        s_fo  += fminf(a.E * b1.z, b1.y * a.RE);   // min(Ea*REb, Eb*REa)
        s_dr  += fminf(a.D * b2.y, b2.x * a.RD);   // min(Da*RDb, Db*RDa)
    }

    g_part[blockIdx.y][i][0] = make_float4(s_dt, s_sky, s_ms, s_fo);
    g_part[blockIdx.y][i][1] = make_float4(s_dr, s_dp, s_ra, s_de);
}

// ---------------------------------------------------------------------------
// Reduce partials (fixed order) + MLP + LayerNorm + GELU(exact) + out
// ---------------------------------------------------------------------------
__global__ void __launch_bounds__(256) finish_kernel(
    const float* __restrict__ W1, const float* __restrict__ b1,
    const float* __restrict__ ln_g, const float* __restrict__ ln_b,
    const float* __restrict__ W2, const float* __restrict__ b2,
    float* __restrict__ out)
{
    __shared__ float sW1[8 * 32];
    __shared__ float sW2[32 * 16];
    __shared__ float sb1[32], sg[32], sbeta[32], sb2[16];

    for (int k = threadIdx.x; k < 256; k += blockDim.x) sW1[k] = W1[k];
    for (int k = threadIdx.x; k < 512; k += blockDim.x) sW2[k] = W2[k];
    if (threadIdx.x < 32) {
        sb1[threadIdx.x]   = b1[threadIdx.x];
        sg[threadIdx.x]    = ln_g[threadIdx.x];
        sbeta[threadIdx.x] = ln_b[threadIdx.x];
        if (threadIdx.x < 16) sb2[threadIdx.x] = b2[threadIdx.x];
    }
    __syncthreads();

    const int i = blockIdx.x * blockDim.x + threadIdx.x;
    if (i >= N) return;

    float4 t0 = make_float4(0.f, 0.f, 0.f, 0.f);
    float4 t1 = make_float4(0.f, 0.f, 0.f, 0.f);
    #pragma unroll
    for (int c = 0; c < NJ; ++c) {
        float4 p0 = g_part[c][i][0];
        float4 p1 = g_part[c][i][1];
        t0.x += p0.x; t0.y += p0.y; t0.z += p0.z; t0.w += p0.w;
        t1.x += p1.x; t1.y += p1.y; t1.z += p1.z; t1.w += p1.w;
    }

    // diag = [0,0,1,1,1,0,0,0]; self-pair contributes ~exactly that. /(n-1).
    const float inv = 1.0f / (float)(N - 1);
    float x[8];
    x[0] = t0.x * inv;
    x[1] = t0.y * inv;
    x[2] = (t0.z - 1.0f) * inv;
    x[3] = (t0.w - 1.0f) * inv;
    x[4] = (t1.x - 1.0f) * inv;
    x[5] = t1.y * inv;
    x[6] = t1.z * inv;
    x[7] = t1.w * inv;

    float h[32];
    #pragma unroll
    for (int k = 0; k < 32; ++k) {
        float acc = sb1[k];
        #pragma unroll
        for (int f = 0; f < 8; ++f)
            acc = fmaf(x[f], sW1[f * 32 + k], acc);
        h[k] = acc;
    }

    float mu = 0.f;
    #pragma unroll
    for (int k = 0; k < 32; ++k) mu += h[k];
    mu *= (1.0f / 32.0f);
    float var = 0.f;
    #pragma unroll
    for (int k = 0; k < 32; ++k) {
        float d = h[k] - mu;
        var = fmaf(d, d, var);
    }
    var *= (1.0f / 32.0f);
    float rs = rsqrtf(var + 1e-5f);

    #pragma unroll
    for (int k = 0; k < 32; ++k) {
        float v = fmaf((h[k] - mu) * rs, sg[k], sbeta[k]);
        h[k] = 0.5f * v * (1.0f + erff(v * 0.7071067811865475f));
    }

    float o[16];
    #pragma unroll
    for (int oo = 0; oo < 16; ++oo) {
        float acc = sb2[oo];
        #pragma unroll
        for (int k = 0; k < 32; ++k)
            acc = fmaf(h[k], sW2[k * 16 + oo], acc);
        o[oo] = acc;
    }
    float4* op = reinterpret_cast<float4*>(out + i * 16);
    op[0] = make_float4(o[0],  o[1],  o[2],  o[3]);
    op[1] = make_float4(o[4],  o[5],  o[6],  o[7]);
    op[2] = make_float4(o[8],  o[9],  o[10], o[11]);
    op[3] = make_float4(o[12], o[13], o[14], o[15]);
}

extern "C" void kernel_launch(void* const* d_in, const int* in_sizes, int n_in,
                              void* d_out, int out_size) {
    const float* params = (const float*)d_in[0];
    const float* W1     = (const float*)d_in[1];
    const float* b1     = (const float*)d_in[2];
    const float* ln_g   = (const float*)d_in[3];
    const float* ln_b   = (const float*)d_in[4];
    const float* W2     = (const float*)d_in[5];
    const float* b2     = (const float*)d_in[6];
    float* out = (float*)d_out;

    pairwise_kernel<<<dim3(NBI, NJ), IB>>>(params);
    finish_kernel<<<N / 256, 256>>>(W1, b1, ln_g, ln_b, W2, b2, out);
}